// round 7
// baseline (speedup 1.0000x reference)
#include <cuda_runtime.h>
#include <cuda_bf16.h>
#include <math.h>
#include <stdint.h>

// ---------------- problem constants ----------------
#define Bsz   64
#define Nn    200      // seq len == state dim
#define Dd    200
#define Mm    50
#define Lb    512
#define Hb    768
#define NUMQ  10000
#define BT    (Bsz*Nn)          // 12800
#define MV_PER_B 2010000L       // 201*50*200
#define OUT_P_SIZE   12800L
#define OUT_MV_SIZE  128640000L
#define OUT_W_SIZE   640000L

typedef unsigned long long ull;

// ---------------- scratch (static device globals; no runtime alloc) ----------------
__device__ float g_em  [ (long)Bsz*Lb*Dd ];   // [64,512,200]  em = bert@W_at.T+b
__device__ float g_VE  [ (long)BT*400 ];      // [b,n, 0:200]=v, [200:400]=em_at row
__device__ float g_RK  [ (long)BT*400 ];      // [b,n, 0:200]=read, [200:400]=k
__device__ float g_e   [ (long)BT*Dd ];
__device__ float g_a   [ (long)BT*Dd ];
__device__ float g_f   [ (long)BT*Dd ];
__device__ float g_fl  [ (long)BT*Dd ];       // f_l_pre [b, i, j] row-major
__device__ float g_wlog[ (long)BT*Mm ];

// ---------------- packed f32x2 helpers (fp32 path for Mv/w-critical GEMMs) ----------------
__device__ __forceinline__ ull dup2(float x) {
    ull r; asm("mov.b64 %0, {%1, %1};" : "=l"(r) : "f"(x)); return r;
}
__device__ __forceinline__ void fma2(ull& d, ull a, ull b) {
    asm("fma.rn.f32x2 %0, %1, %2, %0;" : "+l"(d) : "l"(a), "l"(b));
}
__device__ __forceinline__ float2 unpk2(ull v) {
    float2 f; asm("mov.b64 {%0, %1}, %2;" : "=f"(f.x), "=f"(f.y) : "l"(v)); return f;
}

// ---------------- bf16 MMA helpers ----------------
__device__ __forceinline__ uint32_t cvt2(float lo, float hi) {
    uint32_t r; asm("cvt.rn.bf16x2.f32 %0, %1, %2;" : "=r"(r) : "f"(hi), "f"(lo)); return r;
}
__device__ __forceinline__ uint32_t smem_u32(const void* p) {
    return (uint32_t)__cvta_generic_to_shared(p);
}
__device__ __forceinline__ void ldsm_x4(uint32_t& r0, uint32_t& r1, uint32_t& r2, uint32_t& r3,
                                        uint32_t addr) {
    asm volatile("ldmatrix.sync.aligned.m8n8.x4.shared.b16 {%0,%1,%2,%3}, [%4];"
                 : "=r"(r0), "=r"(r1), "=r"(r2), "=r"(r3) : "r"(addr));
}
__device__ __forceinline__ void mma16816(float* c, const uint32_t* a, const uint32_t* b) {
    asm volatile("mma.sync.aligned.m16n8k16.row.col.f32.bf16.bf16.f32 "
                 "{%0,%1,%2,%3}, {%4,%5,%6,%7}, {%8,%9}, {%0,%1,%2,%3};"
                 : "+f"(c[0]), "+f"(c[1]), "+f"(c[2]), "+f"(c[3])
                 : "r"(a[0]), "r"(a[1]), "r"(a[2]), "r"(a[3]), "r"(b[0]), "r"(b[1]));
}

template<int ACT>
__device__ __forceinline__ float act_f(float v) {
    if (ACT == 1) return 1.f / (1.f + expf(-v));
    if (ACT == 2) return tanhf(v);
    if (ACT == 3) return fmaxf(v, 0.f);
    return v;
}

// ---------------- bf16 tensor-core GEMM: C = act(A @ B^T + bias) ----------------
// fp32 in/out; converts to bf16 on the smem-fill path. fp32 accumulate.
// Block tile 128M x 64N, BK=32, 256 threads (8 warps: 4M x 2N, warp tile 32x32).
template<int ACT, bool TRANS_A>
__global__ __launch_bounds__(256)
void mma_gemm(const float* __restrict__ A, const float* __restrict__ B,
              const float* __restrict__ bias, float* __restrict__ C,
              int M, int N, int K, long sAb, long sCb,
              int lda_row, int lda_k, int ldc)
{
    __shared__ __align__(16) __nv_bfloat16 As[128][40];  // 32 K + 8 pad (80B rows)
    __shared__ __align__(16) __nv_bfloat16 Bs[64][40];
    A += (long)blockIdx.z * sAb;
    C += (long)blockIdx.z * sCb;
    const int tid  = threadIdx.x;
    const int lane = tid & 31, warp = tid >> 5;
    const int wm = (warp >> 1) * 32, wn = (warp & 1) * 32;
    const int m0 = blockIdx.y * 128, n0 = blockIdx.x * 64;

    float c[2][4][4] = {};

    const uint32_t as_base = smem_u32(&As[0][0]);
    const uint32_t bs_base = smem_u32(&Bs[0][0]);
    const uint32_t a_addr0 = as_base + (uint32_t)(wm + (lane & 15)) * 80u + (uint32_t)(lane >> 4) * 16u;
    const uint32_t b_addr0 = bs_base + (uint32_t)(wn + (lane >> 4) * 8 + (lane & 7)) * 80u
                           + (uint32_t)((lane >> 3) & 1) * 16u;

    for (int k0 = 0; k0 < K; k0 += 32) {
        if (!TRANS_A) {
            #pragma unroll
            for (int u = 0; u < 4; u++) {
                int slot = tid + u * 256;
                int row = slot >> 3, kq = (slot & 7) * 4;
                int m = m0 + row;
                float4 v = make_float4(0.f, 0.f, 0.f, 0.f);
                if (m < M) {
                    int k = k0 + kq;
                    if (k + 3 < K) v = *(const float4*)&A[(long)m * lda_row + k];
                    else {
                        float t0 = (k     < K) ? A[(long)m * lda_row + k    ] : 0.f;
                        float t1 = (k + 1 < K) ? A[(long)m * lda_row + k + 1] : 0.f;
                        float t2 = (k + 2 < K) ? A[(long)m * lda_row + k + 2] : 0.f;
                        float t3 = (k + 3 < K) ? A[(long)m * lda_row + k + 3] : 0.f;
                        v = make_float4(t0, t1, t2, t3);
                    }
                }
                uint2 pk; pk.x = cvt2(v.x, v.y); pk.y = cvt2(v.z, v.w);
                *(uint2*)&As[row][kq] = pk;
            }
        } else {
            #pragma unroll
            for (int u = 0; u < 16; u++) {
                int idx = tid + u * 256;
                int mm = idx & 127, kk = idx >> 7;
                int m = m0 + mm, k = k0 + kk;
                float v = (m < M && k < K) ? A[(long)m * lda_row + (long)k * lda_k] : 0.f;
                As[mm][kk] = __float2bfloat16(v);
            }
        }
        #pragma unroll
        for (int u = 0; u < 2; u++) {
            int slot = tid + u * 256;
            int row = slot >> 3, kq = (slot & 7) * 4;
            int n = n0 + row;
            float4 v = make_float4(0.f, 0.f, 0.f, 0.f);
            if (n < N) {
                int k = k0 + kq;
                if (k + 3 < K) v = *(const float4*)&B[(long)n * K + k];
                else {
                    float t0 = (k     < K) ? B[(long)n * K + k    ] : 0.f;
                    float t1 = (k + 1 < K) ? B[(long)n * K + k + 1] : 0.f;
                    float t2 = (k + 2 < K) ? B[(long)n * K + k + 2] : 0.f;
                    float t3 = (k + 3 < K) ? B[(long)n * K + k + 3] : 0.f;
                    v = make_float4(t0, t1, t2, t3);
                }
            }
            uint2 pk; pk.x = cvt2(v.x, v.y); pk.y = cvt2(v.z, v.w);
            *(uint2*)&Bs[row][kq] = pk;
        }
        __syncthreads();
        #pragma unroll
        for (int ks = 0; ks < 2; ks++) {
            uint32_t a[2][4], b[2][4];
            ldsm_x4(a[0][0], a[0][1], a[0][2], a[0][3], a_addr0 + ks * 32u);
            ldsm_x4(a[1][0], a[1][1], a[1][2], a[1][3], a_addr0 + 16u * 80u + ks * 32u);
            ldsm_x4(b[0][0], b[0][1], b[0][2], b[0][3], b_addr0 + ks * 32u);
            ldsm_x4(b[1][0], b[1][1], b[1][2], b[1][3], b_addr0 + 16u * 80u + ks * 32u);
            #pragma unroll
            for (int mt = 0; mt < 2; mt++) {
                mma16816(c[mt][0], a[mt], &b[0][0]);
                mma16816(c[mt][1], a[mt], &b[0][2]);
                mma16816(c[mt][2], a[mt], &b[1][0]);
                mma16816(c[mt][3], a[mt], &b[1][2]);
            }
        }
        __syncthreads();
    }
    #pragma unroll
    for (int mt = 0; mt < 2; mt++) {
        int r0 = m0 + wm + mt * 16 + (lane >> 2);
        #pragma unroll
        for (int nt = 0; nt < 4; nt++) {
            int col = n0 + wn + nt * 8 + (lane & 3) * 2;
            if (col >= N) continue;
            float bb0 = bias ? bias[col] : 0.f;
            bool c1ok = (col + 1 < N);
            float bb1 = c1ok ? (bias ? bias[col + 1] : 0.f) : 0.f;
            if (r0 < M) {
                C[(long)r0 * ldc + col] = act_f<ACT>(c[mt][nt][0] + bb0);
                if (c1ok) C[(long)r0 * ldc + col + 1] = act_f<ACT>(c[mt][nt][1] + bb1);
            }
            if (r0 + 8 < M) {
                C[(long)(r0 + 8) * ldc + col] = act_f<ACT>(c[mt][nt][2] + bb0);
                if (c1ok) C[(long)(r0 + 8) * ldc + col + 1] = act_f<ACT>(c[mt][nt][3] + bb1);
            }
        }
    }
}

// ---------------- fp32 f32x2 GEMM (Mv/w-critical path: wlog) ----------------
template<int ACT, bool TRANS_A>
__global__ __launch_bounds__(256)
void gemm2(const float* __restrict__ A, const float* __restrict__ B,
           const float* __restrict__ bias, float* __restrict__ C,
           int M, int N, int K, long sAb, long sCb,
           int lda_row, int lda_k, int ldc)
{
    __shared__ float As[16][128];   // [k][m]
    __shared__ float Bs[16][64];    // [k][n]
    A += (long)blockIdx.z * sAb;
    C += (long)blockIdx.z * sCb;
    const int tid = threadIdx.x;
    const int tx = tid & 15;
    const int ty = tid >> 4;
    const int m0 = blockIdx.y * 128, n0 = blockIdx.x * 64;

    ull acc[4][4] = {};

    for (int k0 = 0; k0 < K; k0 += 16) {
        const bool ktail = (k0 + 16 > K);
        #pragma unroll
        for (int u = 0; u < 2; u++) {
            int f4  = tid + u * 256;
            int row = f4 >> 2, kq = (f4 & 3) * 4;
            int m = m0 + row;
            float4 v = make_float4(0.f, 0.f, 0.f, 0.f);
            if (m < M) {
                if (!ktail) {
                    v = *(const float4*)&A[(long)m * lda_row + k0 + kq];
                } else {
                    float t4[4];
                    #pragma unroll
                    for (int j = 0; j < 4; j++) {
                        int k = k0 + kq + j;
                        t4[j] = (k < K) ? A[(long)m * lda_row + k] : 0.f;
                    }
                    v = make_float4(t4[0], t4[1], t4[2], t4[3]);
                }
            }
            As[kq + 0][row] = v.x; As[kq + 1][row] = v.y;
            As[kq + 2][row] = v.z; As[kq + 3][row] = v.w;
        }
        {
            int n = tid >> 2, kq = (tid & 3) * 4;
            int nn = n0 + n;
            float4 v = make_float4(0.f, 0.f, 0.f, 0.f);
            if (nn < N) {
                if (!ktail) {
                    v = *(const float4*)&B[(long)nn * K + k0 + kq];
                } else {
                    float t4[4];
                    #pragma unroll
                    for (int j = 0; j < 4; j++) {
                        int k = k0 + kq + j;
                        t4[j] = (k < K) ? B[(long)nn * K + k] : 0.f;
                    }
                    v = make_float4(t4[0], t4[1], t4[2], t4[3]);
                }
            }
            Bs[kq + 0][n] = v.x; Bs[kq + 1][n] = v.y;
            Bs[kq + 2][n] = v.z; Bs[kq + 3][n] = v.w;
        }
        __syncthreads();
        #pragma unroll
        for (int k = 0; k < 16; k++) {
            const ull* ap = (const ull*)&As[k][ty * 8];
            ull a0 = ap[0], a1 = ap[1], a2 = ap[2], a3 = ap[3];
            float4 bv = *(const float4*)&Bs[k][tx * 4];
            ull b0 = dup2(bv.x), b1 = dup2(bv.y), b2 = dup2(bv.z), b3 = dup2(bv.w);
            fma2(acc[0][0], a0, b0); fma2(acc[0][1], a0, b1);
            fma2(acc[0][2], a0, b2); fma2(acc[0][3], a0, b3);
            fma2(acc[1][0], a1, b0); fma2(acc[1][1], a1, b1);
            fma2(acc[1][2], a1, b2); fma2(acc[1][3], a1, b3);
            fma2(acc[2][0], a2, b0); fma2(acc[2][1], a2, b1);
            fma2(acc[2][2], a2, b2); fma2(acc[2][3], a2, b3);
            fma2(acc[3][0], a3, b0); fma2(acc[3][1], a3, b1);
            fma2(acc[3][2], a3, b2); fma2(acc[3][3], a3, b3);
        }
        __syncthreads();
    }
    #pragma unroll
    for (int mp = 0; mp < 4; mp++) {
        int m = m0 + ty * 8 + mp * 2;
        #pragma unroll
        for (int j = 0; j < 4; j++) {
            int n = n0 + tx * 4 + j;
            if (n >= N) continue;
            float2 c2 = unpk2(acc[mp][j]);
            float bb = bias ? bias[n] : 0.f;
            float v0 = act_f<ACT>(c2.x + bb), v1 = act_f<ACT>(c2.y + bb);
            if (m     < M) C[(long)(m    ) * ldc + n] = v0;
            if (m + 1 < M) C[(long)(m + 1) * ldc + n] = v1;
        }
    }
}

// ---------------- fused dual fp32 GEMM: e = sigmoid(A@B1^T+b1), a = tanh(A@B2^T+b2) ----------------
// Same A tile read once; accumulation order per output identical to gemm2 (bitwise same results).
__global__ __launch_bounds__(256)
void gemm2_dual(const float* __restrict__ A,
                const float* __restrict__ B1, const float* __restrict__ bias1, float* __restrict__ C1,
                const float* __restrict__ B2, const float* __restrict__ bias2, float* __restrict__ C2,
                int M, int N, int K, int lda_row, int ldc)
{
    __shared__ float As[16][128];
    __shared__ float Bs1[16][64];
    __shared__ float Bs2[16][64];
    const int tid = threadIdx.x;
    const int tx = tid & 15;
    const int ty = tid >> 4;
    const int m0 = blockIdx.y * 128, n0 = blockIdx.x * 64;

    ull acc1[4][4] = {}, acc2[4][4] = {};

    for (int k0 = 0; k0 < K; k0 += 16) {
        const bool ktail = (k0 + 16 > K);
        #pragma unroll
        for (int u = 0; u < 2; u++) {
            int f4  = tid + u * 256;
            int row = f4 >> 2, kq = (f4 & 3) * 4;
            int m = m0 + row;
            float4 v = make_float4(0.f, 0.f, 0.f, 0.f);
            if (m < M) {
                if (!ktail) v = *(const float4*)&A[(long)m * lda_row + k0 + kq];
                else {
                    float t4[4];
                    #pragma unroll
                    for (int j = 0; j < 4; j++) {
                        int k = k0 + kq + j;
                        t4[j] = (k < K) ? A[(long)m * lda_row + k] : 0.f;
                    }
                    v = make_float4(t4[0], t4[1], t4[2], t4[3]);
                }
            }
            As[kq + 0][row] = v.x; As[kq + 1][row] = v.y;
            As[kq + 2][row] = v.z; As[kq + 3][row] = v.w;
        }
        {
            int n = tid >> 2, kq = (tid & 3) * 4;
            int nn = n0 + n;
            float4 v1 = make_float4(0.f, 0.f, 0.f, 0.f);
            float4 v2 = make_float4(0.f, 0.f, 0.f, 0.f);
            if (nn < N) {
                if (!ktail) {
                    v1 = *(const float4*)&B1[(long)nn * K + k0 + kq];
                    v2 = *(const float4*)&B2[(long)nn * K + k0 + kq];
                } else {
                    float t1[4], t2[4];
                    #pragma unroll
                    for (int j = 0; j < 4; j++) {
                        int k = k0 + kq + j;
                        t1[j] = (k < K) ? B1[(long)nn * K + k] : 0.f;
                        t2[j] = (k < K) ? B2[(long)nn * K + k] : 0.f;
                    }
                    v1 = make_float4(t1[0], t1[1], t1[2], t1[3]);
                    v2 = make_float4(t2[0], t2[1], t2[2], t2[3]);
                }
            }
            Bs1[kq + 0][n] = v1.x; Bs1[kq + 1][n] = v1.y;
            Bs1[kq + 2][n] = v1.z; Bs1[kq + 3][n] = v1.w;
            Bs2[kq + 0][n] = v2.x; Bs2[kq + 1][n] = v2.y;
            Bs2[kq + 2][n] = v2.z; Bs2[kq + 3][n] = v2.w;
        }
        __syncthreads();
        #pragma unroll
        for (int k = 0; k < 16; k++) {
            const ull* ap = (const ull*)&As[k][ty * 8];
            ull a0 = ap[0], a1 = ap[1], a2 = ap[2], a3 = ap[3];
            float4 bv1 = *(const float4*)&Bs1[k][tx * 4];
            float4 bv2 = *(const float4*)&Bs2[k][tx * 4];
            ull p0 = dup2(bv1.x), p1 = dup2(bv1.y), p2 = dup2(bv1.z), p3 = dup2(bv1.w);
            fma2(acc1[0][0], a0, p0); fma2(acc1[0][1], a0, p1);
            fma2(acc1[0][2], a0, p2); fma2(acc1[0][3], a0, p3);
            fma2(acc1[1][0], a1, p0); fma2(acc1[1][1], a1, p1);
            fma2(acc1[1][2], a1, p2); fma2(acc1[1][3], a1, p3);
            fma2(acc1[2][0], a2, p0); fma2(acc1[2][1], a2, p1);
            fma2(acc1[2][2], a2, p2); fma2(acc1[2][3], a2, p3);
            fma2(acc1[3][0], a3, p0); fma2(acc1[3][1], a3, p1);
            fma2(acc1[3][2], a3, p2); fma2(acc1[3][3], a3, p3);
            ull q0 = dup2(bv2.x), q1 = dup2(bv2.y), q2 = dup2(bv2.z), q3 = dup2(bv2.w);
            fma2(acc2[0][0], a0, q0); fma2(acc2[0][1], a0, q1);
            fma2(acc2[0][2], a0, q2); fma2(acc2[0][3], a0, q3);
            fma2(acc2[1][0], a1, q0); fma2(acc2[1][1], a1, q1);
            fma2(acc2[1][2], a1, q2); fma2(acc2[1][3], a1, q3);
            fma2(acc2[2][0], a2, q0); fma2(acc2[2][1], a2, q1);
            fma2(acc2[2][2], a2, q2); fma2(acc2[2][3], a2, q3);
            fma2(acc2[3][0], a3, q0); fma2(acc2[3][1], a3, q1);
            fma2(acc2[3][2], a3, q2); fma2(acc2[3][3], a3, q3);
        }
        __syncthreads();
    }
    #pragma unroll
    for (int mp = 0; mp < 4; mp++) {
        int m = m0 + ty * 8 + mp * 2;
        #pragma unroll
        for (int j = 0; j < 4; j++) {
            int n = n0 + tx * 4 + j;
            if (n >= N) continue;
            float2 c1 = unpk2(acc1[mp][j]);
            float2 c2 = unpk2(acc2[mp][j]);
            float bb1 = bias1[n], bb2 = bias2[n];
            if (m < M) {
                C1[(long)m * ldc + n] = act_f<1>(c1.x + bb1);
                C2[(long)m * ldc + n] = act_f<2>(c2.x + bb2);
            }
            if (m + 1 < M) {
                C1[(long)(m + 1) * ldc + n] = act_f<1>(c1.y + bb1);
                C2[(long)(m + 1) * ldc + n] = act_f<2>(c2.y + bb2);
            }
        }
    }
}

// ---------------- embedding gather (vectorized float4) ----------------
__global__ void gather_kernel(const int* __restrict__ q, const int* __restrict__ r,
                              const float* __restrict__ k_emb, const float* __restrict__ v_emb,
                              float* __restrict__ RK, float* __restrict__ VE)
{
    int bt = blockIdx.x;
    int j  = threadIdx.x;
    if (j >= 50) return;
    int qv = q[bt];
    int xv = qv + NUMQ * r[bt];
    float4 kv = ((const float4*)(k_emb + (long)qv * Dd))[j];
    float4 vv = ((const float4*)(v_emb + (long)xv * Dd))[j];
    ((float4*)(RK + (long)bt * 400 + 200))[j] = kv;
    ((float4*)(VE + (long)bt * 400))[j]       = vv;
}

// ---------------- row softmax over 50 ----------------
__global__ void softmax50_kernel(const float* __restrict__ lg, float* __restrict__ wout)
{
    int row = blockIdx.x * blockDim.x + threadIdx.x;
    if (row >= BT) return;
    const float* x = lg + (long)row * Mm;
    float e[Mm];
    float mx = -3.4e38f;
    #pragma unroll
    for (int s = 0; s < Mm; s++) { e[s] = x[s]; mx = fmaxf(mx, e[s]); }
    float sum = 0.f;
    #pragma unroll
    for (int s = 0; s < Mm; s++) { e[s] = expf(e[s] - mx); sum += e[s]; }
    float inv = 1.f / sum;
    float* o = wout + (long)row * Mm;
    #pragma unroll
    for (int s = 0; s < Mm; s++) o[s] = e[s] * inv;
}

// ---------------- memory scan v2: s-chunk parallel ----------------
// grid (Bsz, 4); block 256 (250 active = 10 s-chunks x 25 d-pairs).
// Each thread: 5 s-states (float2 over d-pair). read = shared partial-sum over s-chunks.
__global__ __launch_bounds__(256)
void scan_kernel2(const float* __restrict__ w, const float* __restrict__ e,
                  const float* __restrict__ a, const float* __restrict__ Mv0,
                  float* __restrict__ MvOut, float* __restrict__ RK)
{
    const int b   = blockIdx.x;
    const int tid = threadIdx.x;
    const int sc  = tid / 25;          // 0..9  (s-chunk: s in [5sc, 5sc+5))
    const int dp  = tid % 25;          // 0..24
    const bool active = (tid < 250);
    const int d0  = (blockIdx.y * 25 + dp) * 2;   // even d index

    __shared__ float  ws[2][64];       // double-buffered w row (50 used)
    __shared__ float2 rdsh[10][26];    // partial read [sc][dp] (pad to 26)

    float2 mv[5];
    if (active) {
        #pragma unroll
        for (int j = 0; j < 5; j++)
            mv[j] = *(const float2*)&Mv0[(sc * 5 + j) * Dd + d0];
    }
    const float* wb = w + (long)b * Nn * Mm;
    const float* eb = e + (long)b * Nn * Dd;
    const float* ab = a + (long)b * Nn * Dd;
    float* mb = MvOut + (long)b * MV_PER_B;
    float* rb = RK + (long)b * Nn * 400;

    if (tid < 50) ws[0][tid] = wb[tid];
    __syncthreads();

    for (int t = 0; t < Nn; t++) {
        const int cur = t & 1, nxt = cur ^ 1;
        if (active) {
            float2 e2 = *(const float2*)&eb[t * Dd + d0];
            float2 a2 = *(const float2*)&ab[t * Dd + d0];
            float2 rd = make_float2(0.f, 0.f);
            float* mt_ = mb + (long)t * (Mm * Dd);
            #pragma unroll
            for (int j = 0; j < 5; j++) {
                int s = sc * 5 + j;
                float wv = ws[cur][s];
                float2 m = mv[j];
                *(float2*)&mt_[s * Dd + d0] = m;        // Mv_pre emit (STG.64)
                rd.x += wv * m.x;
                rd.y += wv * m.y;
                mv[j].x = m.x + wv * (a2.x - e2.x * m.x);
                mv[j].y = m.y + wv * (a2.y - e2.y * m.y);
            }
            rdsh[sc][dp] = rd;
        }
        if (t + 1 < Nn && tid < 50) ws[nxt][tid] = wb[(t + 1) * Mm + tid];
        __syncthreads();
        if (tid < 25) {                                 // combine 10 s-chunk partials
            float2 acc = rdsh[0][tid];
            #pragma unroll
            for (int s = 1; s < 10; s++) {
                acc.x += rdsh[s][tid].x;
                acc.y += rdsh[s][tid].y;
            }
            *(float2*)&rb[t * 400 + (blockIdx.y * 25 + tid) * 2] = acc;
        }
        __syncthreads();
    }
    if (active) {
        float* mt_ = mb + (long)Nn * (Mm * Dd);         // Mv_last slot
        #pragma unroll
        for (int j = 0; j < 5; j++)
            *(float2*)&mt_[(sc * 5 + j) * Dd + d0] = mv[j];
    }
}

// ---------------- final projection p = sigmoid([f | f_l] . Wp + bp) ----------------
__global__ void p_kernel(const float* __restrict__ f, const float* __restrict__ fl,
                         const float* __restrict__ Wp, const float* __restrict__ bp,
                         float* __restrict__ outp)
{
    int b = blockIdx.x;
    __shared__ float wsh[400];
    for (int i = threadIdx.x; i < 400; i += blockDim.x) wsh[i] = Wp[i];
    __syncthreads();
    int t = blockIdx.y * 128 + threadIdx.x;
    if (t < Nn) {
        float acc = bp[0];
        const float* flb = fl + (long)b * Nn * Dd;
        #pragma unroll 4
        for (int i = 0; i < Nn; i++)
            acc += flb[(long)i * Dd + t] * wsh[200 + i];
        const float4* fb = (const float4*)(f + ((long)b * Nn + t) * Dd);
        #pragma unroll 5
        for (int dq = 0; dq < 50; dq++) {
            float4 v = fb[dq];
            acc += v.x * wsh[dq*4] + v.y * wsh[dq*4+1] + v.z * wsh[dq*4+2] + v.w * wsh[dq*4+3];
        }
        outp[b * Nn + t] = 1.f / (1.f + expf(-acc));
    }
}

// ---------------- host ----------------
extern "C" void kernel_launch(void* const* d_in, const int* in_sizes, int n_in,
                              void* d_out, int out_size)
{
    const int*   q      = (const int*)  d_in[0];
    const int*   r      = (const int*)  d_in[1];
    const float* bert   = (const float*)d_in[2];
    const float* k_emb  = (const float*)d_in[3];
    const float* v_emb  = (const float*)d_in[4];
    const float* Mk     = (const float*)d_in[5];
    const float* Mv0    = (const float*)d_in[6];
    const float* W_at   = (const float*)d_in[7];
    const float* b_at   = (const float*)d_in[8];
    const float* W_at2  = (const float*)d_in[9];
    const float* b_at2  = (const float*)d_in[10];
    const float* W_fus  = (const float*)d_in[11];
    const float* b_fus  = (const float*)d_in[12];
    const float* W_e    = (const float*)d_in[13];
    const float* b_e    = (const float*)d_in[14];
    const float* W_a    = (const float*)d_in[15];
    const float* b_a    = (const float*)d_in[16];
    const float* W_f    = (const float*)d_in[17];
    const float* b_f    = (const float*)d_in[18];
    const float* W_p    = (const float*)d_in[19];
    const float* b_p    = (const float*)d_in[20];

    float* outp  = (float*)d_out;
    float* outMv = outp + OUT_P_SIZE;
    float* outw  = outMv + OUT_MV_SIZE;

    float *em, *VE, *RK, *e_s, *a_s, *f_s, *fl_s, *wlog;
    cudaGetSymbolAddress((void**)&em,   g_em);
    cudaGetSymbolAddress((void**)&VE,   g_VE);
    cudaGetSymbolAddress((void**)&RK,   g_RK);
    cudaGetSymbolAddress((void**)&e_s,  g_e);
    cudaGetSymbolAddress((void**)&a_s,  g_a);
    cudaGetSymbolAddress((void**)&f_s,  g_f);
    cudaGetSymbolAddress((void**)&fl_s, g_fl);
    cudaGetSymbolAddress((void**)&wlog, g_wlog);

    // 1. gather k,v into concat buffers
    gather_kernel<<<BT, 64>>>(q, r, k_emb, v_emb, RK, VE);

    // 2. em = bert @ W_at.T + b_at   (bf16 MMA; p-path only)
    mma_gemm<0,false><<<dim3(4, 256, 1), 256>>>(
        bert, W_at, b_at, em, Bsz*Lb, Dd, Hb, 0, 0, Hb, 1, Dd);

    // 3. em_at[b] = em[b]^T @ W_at2.T + b_at2 -> VE[...,200:400]  (bf16 MMA, TRANS_A)
    mma_gemm<0,true><<<dim3(4, 2, Bsz), 256>>>(
        em, W_at2, b_at2, VE + 200, Dd, Dd, Lb,
        (long)Lb * Dd, (long)Nn * 400, 1, Dd, 400);

    // 4. w logits = k @ Mk.T  (fp32 — feeds softmax/Mv, precision-critical)
    gemm2<0,false><<<dim3(1, 100, 1), 256>>>(
        RK + 200, Mk, (const float*)nullptr, wlog, BT, Mm, Dd, 0, 0, 400, 1, Mm);

    // 5. softmax -> w output
    softmax50_kernel<<<100, 128>>>(wlog, outw);

    // 6. fused e = sigmoid(v@W_e.T+b_e), a = tanh(v@W_a.T+b_a)  (fp32, single A pass)
    gemm2_dual<<<dim3(4, 100, 1), 256>>>(
        VE, W_e, b_e, e_s, W_a, b_a, a_s, BT, Dd, Dd, 400, Dd);

    // 7. memory scan v2: Mv output + read -> RK[...,0:200]
    scan_kernel2<<<dim3(Bsz, 4, 1), 256>>>(outw, e_s, a_s, Mv0, outMv, RK);

    // 8. f = tanh([read|k] @ W_f.T + b_f)   (bf16 MMA; p-path only)
    mma_gemm<2,false><<<dim3(4, 100, 1), 256>>>(
        RK, W_f, b_f, f_s, BT, Dd, 400, 0, 0, 400, 1, Dd);

    // 9. f_l_pre = relu([v|em_at] @ W_fus.T + b_fus)  (bf16 MMA; p-path only)
    mma_gemm<3,false><<<dim3(4, 100, 1), 256>>>(
        VE, W_fus, b_fus, fl_s, BT, Dd, 400, 0, 0, 400, 1, Dd);

    // 10. p
    p_kernel<<<dim3(Bsz, 2, 1), 128>>>(f_s, fl_s, W_p, b_p, outp);
}

// round 11
// speedup vs baseline: 1.3763x; 1.3763x over previous
#include <cuda_runtime.h>
#include <cuda_bf16.h>
#include <math.h>
#include <stdint.h>

// ---------------- problem constants ----------------
#define Bsz   64
#define Nn    200
#define Dd    200
#define Mm    50
#define Lb    512
#define Hb    768
#define NUMQ  10000
#define BT    (Bsz*Nn)          // 12800
#define MV_PER_B 2010000L       // 201*50*200
#define OUT_P_SIZE   12800L
#define OUT_MV_SIZE  128640000L

typedef unsigned long long ull;

// ---------------- scratch (static device globals; no runtime alloc) ----------------
__device__ __nv_bfloat16 g_bertH[ (long)Bsz*Lb*Hb ];   // bf16(bert)
__device__ __nv_bfloat16 g_emT  [ (long)Bsz*Dd*Lb ];   // em transposed: [b][d][l], bf16
__device__ __nv_bfloat16 g_WatH [ Dd*Hb ];
__device__ __nv_bfloat16 g_Wat2H[ Dd*Lb ];
__device__ __nv_bfloat16 g_WfH  [ Dd*400 ];
__device__ __nv_bfloat16 g_WfusH[ Dd*400 ];
__device__ __nv_bfloat16 g_RKH  [ (long)BT*400 ];
__device__ __nv_bfloat16 g_VEH  [ (long)BT*400 ];
__device__ float g_VE  [ (long)BT*400 ];      // [0:200]=v, [200:400]=em_at row
__device__ float g_RK  [ (long)BT*400 ];      // [0:200]=read, [200:400]=k
__device__ float g_e   [ (long)BT*Dd ];
__device__ float g_a   [ (long)BT*Dd ];
__device__ float g_f   [ (long)BT*Dd ];
__device__ float g_fl  [ (long)BT*Dd ];
__device__ float g_wlog[ (long)BT*Mm ];

// ---------------- packed f32x2 helpers ----------------
__device__ __forceinline__ ull dup2(float x) {
    ull r; asm("mov.b64 %0, {%1, %1};" : "=l"(r) : "f"(x)); return r;
}
__device__ __forceinline__ void fma2(ull& d, ull a, ull b) {
    asm("fma.rn.f32x2 %0, %1, %2, %0;" : "+l"(d) : "l"(a), "l"(b));
}
__device__ __forceinline__ float2 unpk2(ull v) {
    float2 f; asm("mov.b64 {%0, %1}, %2;" : "=f"(f.x), "=f"(f.y) : "l"(v)); return f;
}

// ---------------- bf16 MMA helpers ----------------
__device__ __forceinline__ uint32_t cvt2(float lo, float hi) {
    uint32_t r; asm("cvt.rn.bf16x2.f32 %0, %1, %2;" : "=r"(r) : "f"(hi), "f"(lo)); return r;
}
__device__ __forceinline__ uint32_t smem_u32(const void* p) {
    return (uint32_t)__cvta_generic_to_shared(p);
}
__device__ __forceinline__ void ldsm_x4(uint32_t& r0, uint32_t& r1, uint32_t& r2, uint32_t& r3,
                                        uint32_t addr) {
    asm volatile("ldmatrix.sync.aligned.m8n8.x4.shared.b16 {%0,%1,%2,%3}, [%4];"
                 : "=r"(r0), "=r"(r1), "=r"(r2), "=r"(r3) : "r"(addr));
}
__device__ __forceinline__ void mma16816(float* c, const uint32_t* a, const uint32_t* b) {
    asm volatile("mma.sync.aligned.m16n8k16.row.col.f32.bf16.bf16.f32 "
                 "{%0,%1,%2,%3}, {%4,%5,%6,%7}, {%8,%9}, {%0,%1,%2,%3};"
                 : "+f"(c[0]), "+f"(c[1]), "+f"(c[2]), "+f"(c[3])
                 : "r"(a[0]), "r"(a[1]), "r"(a[2]), "r"(a[3]), "r"(b[0]), "r"(b[1]));
}

template<int ACT>
__device__ __forceinline__ float act_f(float v) {
    if (ACT == 1) return 1.f / (1.f + expf(-v));
    if (ACT == 2) return tanhf(v);
    if (ACT == 3) return fmaxf(v, 0.f);
    return v;
}

// ---------------- fp32 -> bf16 conversion kernels ----------------
__global__ void cvt_kernel(const float* __restrict__ src, __nv_bfloat16* __restrict__ dst, long n4)
{
    long i = blockIdx.x * (long)blockDim.x + threadIdx.x;
    if (i >= n4) return;
    float4 v = ((const float4*)src)[i];
    uint2 p; p.x = cvt2(v.x, v.y); p.y = cvt2(v.z, v.w);
    ((uint2*)dst)[i] = p;
}

// all four weight tensors in one launch (float4 granularity; sizes are exact multiples)
__global__ void wcvt_kernel(const float* __restrict__ Wat,  const float* __restrict__ Wat2,
                            const float* __restrict__ Wf,   const float* __restrict__ Wfus,
                            __nv_bfloat16* __restrict__ WatH,  __nv_bfloat16* __restrict__ Wat2H,
                            __nv_bfloat16* __restrict__ WfH,   __nv_bfloat16* __restrict__ WfusH)
{
    long i = blockIdx.x * 256L + threadIdx.x;   // float4 index
    const float* s; __nv_bfloat16* d; long off;
    if      (i <  38400) { s = Wat;  d = WatH;  off = i; }
    else if (i <  64000) { s = Wat2; d = Wat2H; off = i - 38400; }
    else if (i <  84000) { s = Wf;   d = WfH;   off = i - 64000; }
    else if (i < 104000) { s = Wfus; d = WfusH; off = i - 84000; }
    else return;
    float4 v = ((const float4*)s)[off];
    uint2 p; p.x = cvt2(v.x, v.y); p.y = cvt2(v.z, v.w);
    ((uint2*)d)[off] = p;
}

// ---------------- bf16-operand tensor-core GEMM: C = act(A @ B^T + bias) ----------------
// A, B pre-converted bf16. Block tile 128M x 64N, BK=32, 256 threads (8 warps, 4Mx2N).
// OUTMODE 0: fp32 C[m*ldc+n].  OUTMODE 1: bf16 transposed-per-512 batch: C[((m>>9)*Dd+n)*Lb + (m&511)].
template<int ACT, int OUTMODE>
__global__ __launch_bounds__(256)
void mma_gemmH(const __nv_bfloat16* __restrict__ A, const __nv_bfloat16* __restrict__ B,
               const float* __restrict__ bias, void* __restrict__ Cout,
               int M, int N, int K, long sAb, long sCb, int lda, int ldc)
{
    __shared__ __align__(16) __nv_bfloat16 As[128][40];  // 32 K + 8 pad (80B rows)
    __shared__ __align__(16) __nv_bfloat16 Bs[64][40];
    A += (long)blockIdx.z * sAb;
    const int tid  = threadIdx.x;
    const int lane = tid & 31, warp = tid >> 5;
    const int wm = (warp >> 1) * 32, wn = (warp & 1) * 32;
    const int m0 = blockIdx.y * 128, n0 = blockIdx.x * 64;

    float c[2][4][4] = {};

    const uint32_t as_base = smem_u32(&As[0][0]);
    const uint32_t bs_base = smem_u32(&Bs[0][0]);
    const uint32_t a_addr0 = as_base + (uint32_t)(wm + (lane & 15)) * 80u + (uint32_t)(lane >> 4) * 16u;
    const uint32_t b_addr0 = bs_base + (uint32_t)(wn + (lane >> 4) * 8 + (lane & 7)) * 80u
                           + (uint32_t)((lane >> 3) & 1) * 16u;

    for (int k0 = 0; k0 < K; k0 += 32) {
        // ---- fill As (128x32 bf16): 2 x 16B per thread ----
        #pragma unroll
        for (int u = 0; u < 2; u++) {
            int slot = tid + u * 256;            // 512 16B slots
            int row = slot >> 2, q = slot & 3;
            int m = m0 + row, k = k0 + q * 8;
            uint4 v = make_uint4(0u, 0u, 0u, 0u);
            if (m < M && k < K)                  // K % 8 == 0 for all uses
                v = *(const uint4*)&A[(long)m * lda + k];
            *(uint4*)&As[row][q * 8] = v;
        }
        // ---- fill Bs (64x32 bf16): 1 x 16B per thread ----
        {
            int n = tid >> 2, q = tid & 3;
            int nn = n0 + n, k = k0 + q * 8;
            uint4 v = make_uint4(0u, 0u, 0u, 0u);
            if (nn < N && k < K)
                v = *(const uint4*)&B[(long)nn * K + k];
            *(uint4*)&Bs[n][q * 8] = v;
        }
        __syncthreads();
        #pragma unroll
        for (int ks = 0; ks < 2; ks++) {
            uint32_t a[2][4], b[2][4];
            ldsm_x4(a[0][0], a[0][1], a[0][2], a[0][3], a_addr0 + ks * 32u);
            ldsm_x4(a[1][0], a[1][1], a[1][2], a[1][3], a_addr0 + 16u * 80u + ks * 32u);
            ldsm_x4(b[0][0], b[0][1], b[0][2], b[0][3], b_addr0 + ks * 32u);
            ldsm_x4(b[1][0], b[1][1], b[1][2], b[1][3], b_addr0 + 16u * 80u + ks * 32u);
            #pragma unroll
            for (int mt = 0; mt < 2; mt++) {
                mma16816(c[mt][0], a[mt], &b[0][0]);
                mma16816(c[mt][1], a[mt], &b[0][2]);
                mma16816(c[mt][2], a[mt], &b[1][0]);
                mma16816(c[mt][3], a[mt], &b[1][2]);
            }
        }
        __syncthreads();
    }
    // ---- epilogue ----
    #pragma unroll
    for (int mt = 0; mt < 2; mt++) {
        int r0 = m0 + wm + mt * 16 + (lane >> 2);
        #pragma unroll
        for (int nt = 0; nt < 4; nt++) {
            int col = n0 + wn + nt * 8 + (lane & 3) * 2;
            if (col >= N) continue;
            float bb0 = bias ? bias[col] : 0.f;
            bool c1ok = (col + 1 < N);
            float bb1 = c1ok ? (bias ? bias[col + 1] : 0.f) : 0.f;
            #pragma unroll
            for (int rr = 0; rr < 2; rr++) {
                int m = r0 + rr * 8;
                if (m >= M) continue;
                float v0 = act_f<ACT>(c[mt][nt][rr * 2 + 0] + bb0);
                float v1 = act_f<ACT>(c[mt][nt][rr * 2 + 1] + bb1);
                if (OUTMODE == 0) {
                    float* C = (float*)Cout + (long)blockIdx.z * sCb;
                    C[(long)m * ldc + col] = v0;
                    if (c1ok) C[(long)m * ldc + col + 1] = v1;
                } else {
                    __nv_bfloat16* C = (__nv_bfloat16*)Cout;
                    long base = ((long)(m >> 9) * Dd) * Lb + (long)(m & 511);
                    C[base + (long)col * Lb] = __float2bfloat16(v0);
                    if (c1ok) C[base + (long)(col + 1) * Lb] = __float2bfloat16(v1);
                }
            }
        }
    }
}

// ---------------- fp32 f32x2 GEMM (wlog) ----------------
// K-guard restored: K % 4 == 0 for all uses, so a float4 never straddles K.
template<int ACT>
__global__ __launch_bounds__(256)
void gemm2(const float* __restrict__ A, const float* __restrict__ B,
           const float* __restrict__ bias, float* __restrict__ C,
           int M, int N, int K, int lda_row, int ldc)
{
    __shared__ float As[16][128];
    __shared__ float Bs[16][64];
    const int tid = threadIdx.x;
    const int tx = tid & 15;
    const int ty = tid >> 4;
    const int m0 = blockIdx.y * 128, n0 = blockIdx.x * 64;

    ull acc[4][4] = {};

    for (int k0 = 0; k0 < K; k0 += 16) {
        #pragma unroll
        for (int u = 0; u < 2; u++) {
            int f4  = tid + u * 256;
            int row = f4 >> 2, kq = (f4 & 3) * 4;
            int m = m0 + row;
            float4 v = make_float4(0.f, 0.f, 0.f, 0.f);
            if (m < M && k0 + kq < K)                     // K-guard (K%4==0)
                v = *(const float4*)&A[(long)m * lda_row + k0 + kq];
            As[kq + 0][row] = v.x; As[kq + 1][row] = v.y;
            As[kq + 2][row] = v.z; As[kq + 3][row] = v.w;
        }
        {
            int n = tid >> 2, kq = (tid & 3) * 4;
            int nn = n0 + n;
            float4 v = make_float4(0.f, 0.f, 0.f, 0.f);
            if (nn < N && k0 + kq < K)                    // K-guard
                v = *(const float4*)&B[(long)nn * K + k0 + kq];
            Bs[kq + 0][n] = v.x; Bs[kq + 1][n] = v.y;
            Bs[kq + 2][n] = v.z; Bs[kq + 3][n] = v.w;
        }
        __syncthreads();
        #pragma unroll
        for (int k = 0; k < 16; k++) {
            const ull* ap = (const ull*)&As[k][ty * 8];
            ull a0 = ap[0], a1 = ap[1], a2 = ap[2], a3 = ap[3];
            float4 bv = *(const float4*)&Bs[k][tx * 4];
            ull b0 = dup2(bv.x), b1 = dup2(bv.y), b2 = dup2(bv.z), b3 = dup2(bv.w);
            fma2(acc[0][0], a0, b0); fma2(acc[0][1], a0, b1);
            fma2(acc[0][2], a0, b2); fma2(acc[0][3], a0, b3);
            fma2(acc[1][0], a1, b0); fma2(acc[1][1], a1, b1);
            fma2(acc[1][2], a1, b2); fma2(acc[1][3], a1, b3);
            fma2(acc[2][0], a2, b0); fma2(acc[2][1], a2, b1);
            fma2(acc[2][2], a2, b2); fma2(acc[2][3], a2, b3);
            fma2(acc[3][0], a3, b0); fma2(acc[3][1], a3, b1);
            fma2(acc[3][2], a3, b2); fma2(acc[3][3], a3, b3);
        }
        __syncthreads();
    }
    #pragma unroll
    for (int mp = 0; mp < 4; mp++) {
        int m = m0 + ty * 8 + mp * 2;
        #pragma unroll
        for (int j = 0; j < 4; j++) {
            int n = n0 + tx * 4 + j;
            if (n >= N) continue;
            float2 c2 = unpk2(acc[mp][j]);
            float bb = bias ? bias[n] : 0.f;
            float v0 = act_f<ACT>(c2.x + bb), v1 = act_f<ACT>(c2.y + bb);
            if (m     < M) C[(long)(m    ) * ldc + n] = v0;
            if (m + 1 < M) C[(long)(m + 1) * ldc + n] = v1;
        }
    }
}

// ---------------- fused dual fp32 GEMM: e = sigmoid, a = tanh ----------------
// K-guard restored (identical fix as gemm2).
__global__ __launch_bounds__(256)
void gemm2_dual(const float* __restrict__ A,
                const float* __restrict__ B1, const float* __restrict__ bias1, float* __restrict__ C1,
                const float* __restrict__ B2, const float* __restrict__ bias2, float* __restrict__ C2,
                int M, int N, int K, int lda_row, int ldc)
{
    __shared__ float As[16][128];
    __shared__ float Bs1[16][64];
    __shared__ float Bs2[16][64];
    const int tid = threadIdx.x;
    const int tx = tid & 15;
    const int ty = tid >> 4;
    const int m0 = blockIdx.y * 128, n0 = blockIdx.x * 64;

    ull acc1[4][4] = {}, acc2[4][4] = {};

    for (int k0 = 0; k0 < K; k0 += 16) {
        #pragma unroll
        for (int u = 0; u < 2; u++) {
            int f4  = tid + u * 256;
            int row = f4 >> 2, kq = (f4 & 3) * 4;
            int m = m0 + row;
            float4 v = make_float4(0.f, 0.f, 0.f, 0.f);
            if (m < M && k0 + kq < K)                     // K-guard (K%4==0)
                v = *(const float4*)&A[(long)m * lda_row + k0 + kq];
            As[kq + 0][row] = v.x; As[kq + 1][row] = v.y;
            As[kq + 2][row] = v.z; As[kq + 3][row] = v.w;
        }
        {
            int n = tid >> 2, kq = (tid & 3) * 4;
            int nn = n0 + n;
            float4 v1 = make_float4(0.f, 0.f, 0.f, 0.f);
            float4 v2 = make_float4(0.f, 0.f, 0.f, 0.f);
            if (nn < N && k0 + kq < K) {                  // K-guard
                v1 = *(const float4*)&B1[(long)nn * K + k0 + kq];
                v2 = *(const float4*)&B2[(long)nn * K + k0 + kq];
            }
            Bs1[kq + 0][n] = v1.x; Bs1[kq + 1][n] = v1.y;
            Bs1[kq + 2][n] = v1.z; Bs1[kq + 3][n] = v1.w;
            Bs2[kq + 0][n] = v2.x; Bs2[kq + 1][n] = v2.y;
            Bs2[kq + 2][n] = v2.z; Bs2[kq + 3][n] = v2.w;
        }
        __syncthreads();
        #pragma unroll
        for (int k = 0; k < 16; k++) {
            const ull* ap = (const ull*)&As[k][ty * 8];
            ull a0 = ap[0], a1 = ap[1], a2 = ap[2], a3 = ap[3];
            float4 bv1 = *(const float4*)&Bs1[k][tx * 4];
            float4 bv2 = *(const float4*)&Bs2[k][tx * 4];
            ull p0 = dup2(bv1.x), p1 = dup2(bv1.y), p2 = dup2(bv1.z), p3 = dup2(bv1.w);
            fma2(acc1[0][0], a0, p0); fma2(acc1[0][1], a0, p1);
            fma2(acc1[0][2], a0, p2); fma2(acc1[0][3], a0, p3);
            fma2(acc1[1][0], a1, p0); fma2(acc1[1][1], a1, p1);
            fma2(acc1[1][2], a1, p2); fma2(acc1[1][3], a1, p3);
            fma2(acc1[2][0], a2, p0); fma2(acc1[2][1], a2, p1);
            fma2(acc1[2][2], a2, p2); fma2(acc1[2][3], a2, p3);
            fma2(acc1[3][0], a3, p0); fma2(acc1[3][1], a3, p1);
            fma2(acc1[3][2], a3, p2); fma2(acc1[3][3], a3, p3);
            ull q0 = dup2(bv2.x), q1 = dup2(bv2.y), q2 = dup2(bv2.z), q3 = dup2(bv2.w);
            fma2(acc2[0][0], a0, q0); fma2(acc2[0][1], a0, q1);
            fma2(acc2[0][2], a0, q2); fma2(acc2[0][3], a0, q3);
            fma2(acc2[1][0], a1, q0); fma2(acc2[1][1], a1, q1);
            fma2(acc2[1][2], a1, q2); fma2(acc2[1][3], a1, q3);
            fma2(acc2[2][0], a2, q0); fma2(acc2[2][1], a2, q1);
            fma2(acc2[2][2], a2, q2); fma2(acc2[2][3], a2, q3);
            fma2(acc2[3][0], a3, q0); fma2(acc2[3][1], a3, q1);
            fma2(acc2[3][2], a3, q2); fma2(acc2[3][3], a3, q3);
        }
        __syncthreads();
    }
    #pragma unroll
    for (int mp = 0; mp < 4; mp++) {
        int m = m0 + ty * 8 + mp * 2;
        #pragma unroll
        for (int j = 0; j < 4; j++) {
            int n = n0 + tx * 4 + j;
            if (n >= N) continue;
            float2 c1 = unpk2(acc1[mp][j]);
            float2 c2 = unpk2(acc2[mp][j]);
            float bb1 = bias1[n], bb2 = bias2[n];
            if (m < M) {
                C1[(long)m * ldc + n] = act_f<1>(c1.x + bb1);
                C2[(long)m * ldc + n] = act_f<2>(c2.x + bb2);
            }
            if (m + 1 < M) {
                C1[(long)(m + 1) * ldc + n] = act_f<1>(c1.y + bb1);
                C2[(long)(m + 1) * ldc + n] = act_f<2>(c2.y + bb2);
            }
        }
    }
}

// ---------------- embedding gather ----------------
__global__ void gather_kernel(const int* __restrict__ q, const int* __restrict__ r,
                              const float* __restrict__ k_emb, const float* __restrict__ v_emb,
                              float* __restrict__ RK, float* __restrict__ VE)
{
    int bt = blockIdx.x;
    int j  = threadIdx.x;
    if (j >= 50) return;
    int qv = q[bt];
    int xv = qv + NUMQ * r[bt];
    float4 kv = ((const float4*)(k_emb + (long)qv * Dd))[j];
    float4 vv = ((const float4*)(v_emb + (long)xv * Dd))[j];
    ((float4*)(RK + (long)bt * 400 + 200))[j] = kv;
    ((float4*)(VE + (long)bt * 400))[j]       = vv;
}

// ---------------- row softmax over 50 ----------------
__global__ void softmax50_kernel(const float* __restrict__ lg, float* __restrict__ wout)
{
    int row = blockIdx.x * blockDim.x + threadIdx.x;
    if (row >= BT) return;
    const float* x = lg + (long)row * Mm;
    float e[Mm];
    float mx = -3.4e38f;
    #pragma unroll
    for (int s = 0; s < Mm; s++) { e[s] = x[s]; mx = fmaxf(mx, e[s]); }
    float sum = 0.f;
    #pragma unroll
    for (int s = 0; s < Mm; s++) { e[s] = expf(e[s] - mx); sum += e[s]; }
    float inv = 1.f / sum;
    float* o = wout + (long)row * Mm;
    #pragma unroll
    for (int s = 0; s < Mm; s++) o[s] = e[s] * inv;
}

// ---------------- memory scan (round-4 proven version) ----------------
__global__ void scan_kernel(const float* __restrict__ w, const float* __restrict__ e,
                            const float* __restrict__ a, const float* __restrict__ Mv0,
                            float* __restrict__ MvOut, float* __restrict__ RK)
{
    int b = blockIdx.x;
    int d = blockIdx.y * 50 + threadIdx.x;
    bool active = (threadIdx.x < 50);
    __shared__ float ws[Mm];
    float mv[Mm];
    if (active) {
        #pragma unroll
        for (int s = 0; s < Mm; s++) mv[s] = Mv0[s * Dd + d];
    }
    const float* wb = w + (long)b * Nn * Mm;
    const float* eb = e + (long)b * Nn * Dd;
    const float* ab = a + (long)b * Nn * Dd;
    float* mb = MvOut + (long)b * MV_PER_B;
    float* rb = RK + (long)b * Nn * 400;

    for (int t = 0; t < Nn; t++) {
        if (threadIdx.x < Mm) ws[threadIdx.x] = wb[t * Mm + threadIdx.x];
        __syncthreads();
        if (active) {
            float ed = eb[t * Dd + d];
            float ad = ab[t * Dd + d];
            float* mp = mb + (long)t * (Mm * Dd) + d;
            float rd = 0.f;
            #pragma unroll
            for (int s = 0; s < Mm; s++) {
                float m_ = mv[s];
                mp[s * Dd] = m_;
                float wv = ws[s];
                rd += wv * m_;
                mv[s] = m_ + wv * (ad - ed * m_);
            }
            rb[t * 400 + d] = rd;
        }
        __syncthreads();
    }
    if (active) {
        float* mp = mb + (long)Nn * (Mm * Dd) + d;
        #pragma unroll
        for (int s = 0; s < Mm; s++) mp[s * Dd] = mv[s];
    }
}

// ---------------- final projection ----------------
__global__ void p_kernel(const float* __restrict__ f, const float* __restrict__ fl,
                         const float* __restrict__ Wp, const float* __restrict__ bp,
                         float* __restrict__ outp)
{
    int b = blockIdx.x;
    __shared__ float wsh[400];
    for (int i = threadIdx.x; i < 400; i += blockDim.x) wsh[i] = Wp[i];
    __syncthreads();
    int t = blockIdx.y * 128 + threadIdx.x;
    if (t < Nn) {
        float acc = bp[0];
        const float* flb = fl + (long)b * Nn * Dd;
        #pragma unroll 4
        for (int i = 0; i < Nn; i++)
            acc += flb[(long)i * Dd + t] * wsh[200 + i];
        const float4* fb = (const float4*)(f + ((long)b * Nn + t) * Dd);
        #pragma unroll 5
        for (int dq = 0; dq < 50; dq++) {
            float4 v = fb[dq];
            acc += v.x * wsh[dq*4] + v.y * wsh[dq*4+1] + v.z * wsh[dq*4+2] + v.w * wsh[dq*4+3];
        }
        outp[b * Nn + t] = 1.f / (1.f + expf(-acc));
    }
}

// ---------------- host ----------------
extern "C" void kernel_launch(void* const* d_in, const int* in_sizes, int n_in,
                              void* d_out, int out_size)
{
    const int*   q      = (const int*)  d_in[0];
    const int*   r      = (const int*)  d_in[1];
    const float* bert   = (const float*)d_in[2];
    const float* k_emb  = (const float*)d_in[3];
    const float* v_emb  = (const float*)d_in[4];
    const float* Mk     = (const float*)d_in[5];
    const float* Mv0    = (const float*)d_in[6];
    const float* W_at   = (const float*)d_in[7];
    const float* b_at   = (const float*)d_in[8];
    const float* W_at2  = (const float*)d_in[9];
    const float* b_at2  = (const float*)d_in[10];
    const float* W_fus  = (const float*)d_in[11];
    const float* b_fus  = (const float*)d_in[12];
    const float* W_e    = (const float*)d_in[13];
    const float* b_e    = (const float*)d_in[14];
    const float* W_a    = (const float*)d_in[15];
    const float* b_a    = (const float*)d_in[16];
    const float* W_f    = (const float*)d_in[17];
    const float* b_f    = (const float*)d_in[18];
    const float* W_p    = (const float*)d_in[19];
    const float* b_p    = (const float*)d_in[20];

    float* outp  = (float*)d_out;
    float* outMv = outp + OUT_P_SIZE;
    float* outw  = outMv + OUT_MV_SIZE;

    __nv_bfloat16 *bertH, *emT, *WatH, *Wat2H, *WfH, *WfusH, *RKH, *VEH;
    float *VE, *RK, *e_s, *a_s, *f_s, *fl_s, *wlog;
    cudaGetSymbolAddress((void**)&bertH, g_bertH);
    cudaGetSymbolAddress((void**)&emT,   g_emT);
    cudaGetSymbolAddress((void**)&WatH,  g_WatH);
    cudaGetSymbolAddress((void**)&Wat2H, g_Wat2H);
    cudaGetSymbolAddress((void**)&WfH,   g_WfH);
    cudaGetSymbolAddress((void**)&WfusH, g_WfusH);
    cudaGetSymbolAddress((void**)&RKH,   g_RKH);
    cudaGetSymbolAddress((void**)&VEH,   g_VEH);
    cudaGetSymbolAddress((void**)&VE,    g_VE);
    cudaGetSymbolAddress((void**)&RK,    g_RK);
    cudaGetSymbolAddress((void**)&e_s,   g_e);
    cudaGetSymbolAddress((void**)&a_s,   g_a);
    cudaGetSymbolAddress((void**)&f_s,   g_f);
    cudaGetSymbolAddress((void**)&fl_s,  g_fl);
    cudaGetSymbolAddress((void**)&wlog,  g_wlog);

    // 1. gather k,v
    gather_kernel<<<BT, 64>>>(q, r, k_emb, v_emb, RK, VE);

    // 2. bertH = bf16(bert)   (25.17M elems = 6291456 float4)
    cvt_kernel<<<24576, 256>>>(bert, bertH, 6291456L);

    // 3. weights -> bf16 (one launch)
    wcvt_kernel<<<407, 256>>>(W_at, W_at2, W_f, W_fus, WatH, Wat2H, WfH, WfusH);

    // 4. em = bertH @ WatH^T + b_at -> bf16 transposed em_T[b][d][l]
    mma_gemmH<0,1><<<dim3(4, 256, 1), 256>>>(
        bertH, WatH, b_at, emT, Bsz*Lb, Dd, Hb, 0, 0, Hb, 0);

    // 5. em_at[b] = em_T[b] @ Wat2H^T + b_at2 -> VE[...,200:400] fp32
    mma_gemmH<0,0><<<dim3(4, 2, Bsz), 256>>>(
        emT, Wat2H, b_at2, VE + 200, Dd, Dd, Lb,
        (long)Dd * Lb, (long)Nn * 400, Lb, 400);

    // 6. w logits = k @ Mk^T  (fp32, precision-critical)
    gemm2<0><<<dim3(1, 100, 1), 256>>>(
        RK + 200, Mk, (const float*)nullptr, wlog, BT, Mm, Dd, 400, Mm);

    // 7. softmax -> w output
    softmax50_kernel<<<100, 128>>>(wlog, outw);

    // 8. fused e/a (fp32)
    gemm2_dual<<<dim3(4, 100, 1), 256>>>(
        VE, W_e, b_e, e_s, W_a, b_a, a_s, BT, Dd, Dd, 400, Dd);

    // 9. memory scan (round-4 version)
    scan_kernel<<<dim3(Bsz, 4, 1), 64>>>(outw, e_s, a_s, Mv0, outMv, RK);

    // 10/11. RKH, VEH bf16 copies (5.12M elems = 1280000 float4 each)
    cvt_kernel<<<5000, 256>>>(RK, RKH, 1280000L);
    cvt_kernel<<<5000, 256>>>(VE, VEH, 1280000L);

    // 12. f = tanh(RKH @ WfH^T + b_f)
    mma_gemmH<2,0><<<dim3(4, 100, 1), 256>>>(
        RKH, WfH, b_f, f_s, BT, Dd, 400, 0, 0, 400, Dd);

    // 13. f_l = relu(VEH @ WfusH^T + b_fus)
    mma_gemmH<3,0><<<dim3(4, 100, 1), 256>>>(
        VEH, WfusH, b_fus, fl_s, BT, Dd, 400, 0, 0, 400, Dd);

    // 14. p
    p_kernel<<<dim3(Bsz, 2, 1), 128>>>(f_s, fl_s, W_p, b_p, outp);
}

// round 16
// speedup vs baseline: 1.3940x; 1.0128x over previous
#include <cuda_runtime.h>
#include <cuda_bf16.h>
#include <math.h>
#include <stdint.h>

// ---------------- problem constants ----------------
#define Bsz   64
#define Nn    200
#define Dd    200
#define Mm    50
#define Lb    512
#define Hb    768
#define NUMQ  10000
#define BT    (Bsz*Nn)          // 12800
#define MV_PER_B 2010000L       // 201*50*200
#define OUT_P_SIZE   12800L
#define OUT_MV_SIZE  128640000L

typedef unsigned long long ull;

// ---------------- scratch (static device globals; no runtime alloc) ----------------
__device__ __nv_bfloat16 g_bertH[ (long)Bsz*Lb*Hb ];   // bf16(bert)
__device__ __nv_bfloat16 g_emT  [ (long)Bsz*Dd*Lb ];   // em transposed: [b][d][l], bf16
__device__ __nv_bfloat16 g_WatH [ Dd*Hb ];
__device__ __nv_bfloat16 g_Wat2H[ Dd*Lb ];
__device__ __nv_bfloat16 g_WfH  [ Dd*400 ];
__device__ __nv_bfloat16 g_WfusH[ Dd*400 ];
__device__ __nv_bfloat16 g_RKH  [ (long)BT*400 ];      // [0:200]=read (scan), [200:400]=k (gather)
__device__ __nv_bfloat16 g_VEH  [ (long)BT*400 ];      // [0:200]=v (gather), [200:400]=em_at (GEMM)
__device__ float g_VE  [ (long)BT*400 ];      // [0:200]=v fp32 (for e/a GEMM); [200:400] unused
__device__ float g_RK  [ (long)BT*400 ];      // [200:400]=k fp32 (for wlog);   [0:200] unused
__device__ float g_e   [ (long)BT*Dd ];
__device__ float g_a   [ (long)BT*Dd ];
__device__ float g_f   [ (long)BT*Dd ];
__device__ float g_fl  [ (long)BT*Dd ];
__device__ float g_wlog[ (long)BT*Mm ];

// ---------------- packed f32x2 helpers ----------------
__device__ __forceinline__ ull dup2(float x) {
    ull r; asm("mov.b64 %0, {%1, %1};" : "=l"(r) : "f"(x)); return r;
}
__device__ __forceinline__ void fma2(ull& d, ull a, ull b) {
    asm("fma.rn.f32x2 %0, %1, %2, %0;" : "+l"(d) : "l"(a), "l"(b));
}
__device__ __forceinline__ float2 unpk2(ull v) {
    float2 f; asm("mov.b64 {%0, %1}, %2;" : "=f"(f.x), "=f"(f.y) : "l"(v)); return f;
}

// ---------------- bf16 MMA helpers ----------------
__device__ __forceinline__ uint32_t cvt2(float lo, float hi) {
    uint32_t r; asm("cvt.rn.bf16x2.f32 %0, %1, %2;" : "=r"(r) : "f"(hi), "f"(lo)); return r;
}
__device__ __forceinline__ uint32_t smem_u32(const void* p) {
    return (uint32_t)__cvta_generic_to_shared(p);
}
__device__ __forceinline__ void ldsm_x4(uint32_t& r0, uint32_t& r1, uint32_t& r2, uint32_t& r3,
                                        uint32_t addr) {
    asm volatile("ldmatrix.sync.aligned.m8n8.x4.shared.b16 {%0,%1,%2,%3}, [%4];"
                 : "=r"(r0), "=r"(r1), "=r"(r2), "=r"(r3) : "r"(addr));
}
__device__ __forceinline__ void mma16816(float* c, const uint32_t* a, const uint32_t* b) {
    asm volatile("mma.sync.aligned.m16n8k16.row.col.f32.bf16.bf16.f32 "
                 "{%0,%1,%2,%3}, {%4,%5,%6,%7}, {%8,%9}, {%0,%1,%2,%3};"
                 : "+f"(c[0]), "+f"(c[1]), "+f"(c[2]), "+f"(c[3])
                 : "r"(a[0]), "r"(a[1]), "r"(a[2]), "r"(a[3]), "r"(b[0]), "r"(b[1]));
}

template<int ACT>
__device__ __forceinline__ float act_f(float v) {
    if (ACT == 1) return 1.f / (1.f + expf(-v));
    if (ACT == 2) return tanhf(v);
    if (ACT == 3) return fmaxf(v, 0.f);
    return v;
}

// ---------------- fp32 -> bf16 conversion kernels ----------------
__global__ void cvt_kernel(const float* __restrict__ src, __nv_bfloat16* __restrict__ dst, long n4)
{
    long i = blockIdx.x * (long)blockDim.x + threadIdx.x;
    if (i >= n4) return;
    float4 v = ((const float4*)src)[i];
    uint2 p; p.x = cvt2(v.x, v.y); p.y = cvt2(v.z, v.w);
    ((uint2*)dst)[i] = p;
}

// all four weight tensors in one launch (float4 granularity; sizes are exact multiples)
__global__ void wcvt_kernel(const float* __restrict__ Wat,  const float* __restrict__ Wat2,
                            const float* __restrict__ Wf,   const float* __restrict__ Wfus,
                            __nv_bfloat16* __restrict__ WatH,  __nv_bfloat16* __restrict__ Wat2H,
                            __nv_bfloat16* __restrict__ WfH,   __nv_bfloat16* __restrict__ WfusH)
{
    long i = blockIdx.x * 256L + threadIdx.x;   // float4 index
    const float* s; __nv_bfloat16* d; long off;
    if      (i <  38400) { s = Wat;  d = WatH;  off = i; }
    else if (i <  64000) { s = Wat2; d = Wat2H; off = i - 38400; }
    else if (i <  84000) { s = Wf;   d = WfH;   off = i - 64000; }
    else if (i < 104000) { s = Wfus; d = WfusH; off = i - 84000; }
    else return;
    float4 v = ((const float4*)s)[off];
    uint2 p; p.x = cvt2(v.x, v.y); p.y = cvt2(v.z, v.w);
    ((uint2*)d)[off] = p;
}

// ---------------- bf16-operand tensor-core GEMM: C = act(A @ B^T + bias) ----------------
// A, B pre-converted bf16. Block tile 128M x 64N, BK=32, 256 threads (8 warps, 4Mx2N).
// Double-buffered global->smem via register prefetch.
// OUTMODE 0: fp32 C[m*ldc+n].
// OUTMODE 1: bf16 transposed-per-512 batch: C[((m>>9)*Dd+n)*Lb + (m&511)].
// OUTMODE 2: bf16 C[m*ldc+n] (with batch stride sCb in elements).
template<int ACT, int OUTMODE>
__global__ __launch_bounds__(256)
void mma_gemmH(const __nv_bfloat16* __restrict__ A, const __nv_bfloat16* __restrict__ B,
               const float* __restrict__ bias, void* __restrict__ Cout,
               int M, int N, int K, long sAb, long sCb, int lda, int ldc)
{
    __shared__ __align__(16) __nv_bfloat16 As[128][40];  // 32 K + 8 pad (80B rows)
    __shared__ __align__(16) __nv_bfloat16 Bs[64][40];
    A += (long)blockIdx.z * sAb;
    const int tid  = threadIdx.x;
    const int lane = tid & 31, warp = tid >> 5;
    const int wm = (warp >> 1) * 32, wn = (warp & 1) * 32;
    const int m0 = blockIdx.y * 128, n0 = blockIdx.x * 64;

    float c[2][4][4] = {};

    const uint32_t as_base = smem_u32(&As[0][0]);
    const uint32_t bs_base = smem_u32(&Bs[0][0]);
    const uint32_t a_addr0 = as_base + (uint32_t)(wm + (lane & 15)) * 80u + (uint32_t)(lane >> 4) * 16u;
    const uint32_t b_addr0 = bs_base + (uint32_t)(wn + (lane >> 4) * 8 + (lane & 7)) * 80u
                           + (uint32_t)((lane >> 3) & 1) * 16u;

    // A-slot/B-slot coordinates (fixed per thread)
    const int a_row0 = (tid      ) >> 2, a_q0 = (tid      ) & 3;
    const int a_row1 = (tid + 256) >> 2, a_q1 = (tid + 256) & 3;
    const int b_row  = tid >> 2,         b_q  = tid & 3;

    // register prefetch buffers
    uint4 pa0, pa1, pb;
    {   // prologue: load k0 = 0
        int k;
        pa0 = make_uint4(0u,0u,0u,0u); pa1 = pa0; pb = pa0;
        k = a_q0 * 8; if (m0 + a_row0 < M && k < K) pa0 = *(const uint4*)&A[(long)(m0 + a_row0) * lda + k];
        k = a_q1 * 8; if (m0 + a_row1 < M && k < K) pa1 = *(const uint4*)&A[(long)(m0 + a_row1) * lda + k];
        k = b_q  * 8; if (n0 + b_row  < N && k < K) pb  = *(const uint4*)&B[(long)(n0 + b_row ) * K   + k];
    }

    for (int k0 = 0; k0 < K; k0 += 32) {
        // store prefetched tile
        *(uint4*)&As[a_row0][a_q0 * 8] = pa0;
        *(uint4*)&As[a_row1][a_q1 * 8] = pa1;
        *(uint4*)&Bs[b_row ][b_q  * 8] = pb;
        __syncthreads();
        // issue next tile's loads early (overlap with MMA)
        if (k0 + 32 < K) {
            int kb = k0 + 32, k;
            pa0 = make_uint4(0u,0u,0u,0u); pa1 = pa0; pb = pa0;
            k = kb + a_q0 * 8; if (m0 + a_row0 < M && k < K) pa0 = *(const uint4*)&A[(long)(m0 + a_row0) * lda + k];
            k = kb + a_q1 * 8; if (m0 + a_row1 < M && k < K) pa1 = *(const uint4*)&A[(long)(m0 + a_row1) * lda + k];
            k = kb + b_q  * 8; if (n0 + b_row  < N && k < K) pb  = *(const uint4*)&B[(long)(n0 + b_row ) * K   + k];
        }
        #pragma unroll
        for (int ks = 0; ks < 2; ks++) {
            uint32_t a[2][4], b[2][4];
            ldsm_x4(a[0][0], a[0][1], a[0][2], a[0][3], a_addr0 + ks * 32u);
            ldsm_x4(a[1][0], a[1][1], a[1][2], a[1][3], a_addr0 + 16u * 80u + ks * 32u);
            ldsm_x4(b[0][0], b[0][1], b[0][2], b[0][3], b_addr0 + ks * 32u);
            ldsm_x4(b[1][0], b[1][1], b[1][2], b[1][3], b_addr0 + 16u * 80u + ks * 32u);
            #pragma unroll
            for (int mt = 0; mt < 2; mt++) {
                mma16816(c[mt][0], a[mt], &b[0][0]);
                mma16816(c[mt][1], a[mt], &b[0][2]);
                mma16816(c[mt][2], a[mt], &b[1][0]);
                mma16816(c[mt][3], a[mt], &b[1][2]);
            }
        }
        __syncthreads();
    }
    // ---- epilogue ----
    #pragma unroll
    for (int mt = 0; mt < 2; mt++) {
        int r0 = m0 + wm + mt * 16 + (lane >> 2);
        #pragma unroll
        for (int nt = 0; nt < 4; nt++) {
            int col = n0 + wn + nt * 8 + (lane & 3) * 2;
            if (col >= N) continue;
            float bb0 = bias ? bias[col] : 0.f;
            bool c1ok = (col + 1 < N);
            float bb1 = c1ok ? (bias ? bias[col + 1] : 0.f) : 0.f;
            #pragma unroll
            for (int rr = 0; rr < 2; rr++) {
                int m = r0 + rr * 8;
                if (m >= M) continue;
                float v0 = act_f<ACT>(c[mt][nt][rr * 2 + 0] + bb0);
                float v1 = act_f<ACT>(c[mt][nt][rr * 2 + 1] + bb1);
                if (OUTMODE == 0) {
                    float* C = (float*)Cout + (long)blockIdx.z * sCb;
                    C[(long)m * ldc + col] = v0;
                    if (c1ok) C[(long)m * ldc + col + 1] = v1;
                } else if (OUTMODE == 1) {
                    __nv_bfloat16* C = (__nv_bfloat16*)Cout;
                    long base = ((long)(m >> 9) * Dd) * Lb + (long)(m & 511);
                    C[base + (long)col * Lb] = __float2bfloat16(v0);
                    if (c1ok) C[base + (long)(col + 1) * Lb] = __float2bfloat16(v1);
                } else {
                    __nv_bfloat16* C = (__nv_bfloat16*)Cout + (long)blockIdx.z * sCb;
                    C[(long)m * ldc + col] = __float2bfloat16(v0);
                    if (c1ok) C[(long)m * ldc + col + 1] = __float2bfloat16(v1);
                }
            }
        }
    }
}

// ---------------- fp32 f32x2 GEMM (wlog) ----------------
// K-guard: K % 4 == 0 for all uses, so a float4 never straddles K.
template<int ACT>
__global__ __launch_bounds__(256)
void gemm2(const float* __restrict__ A, const float* __restrict__ B,
           const float* __restrict__ bias, float* __restrict__ C,
           int M, int N, int K, int lda_row, int ldc)
{
    __shared__ float As[16][128];
    __shared__ float Bs[16][64];
    const int tid = threadIdx.x;
    const int tx = tid & 15;
    const int ty = tid >> 4;
    const int m0 = blockIdx.y * 128, n0 = blockIdx.x * 64;

    ull acc[4][4] = {};

    for (int k0 = 0; k0 < K; k0 += 16) {
        #pragma unroll
        for (int u = 0; u < 2; u++) {
            int f4  = tid + u * 256;
            int row = f4 >> 2, kq = (f4 & 3) * 4;
            int m = m0 + row;
            float4 v = make_float4(0.f, 0.f, 0.f, 0.f);
            if (m < M && k0 + kq < K)                     // K-guard (K%4==0)
                v = *(const float4*)&A[(long)m * lda_row + k0 + kq];
            As[kq + 0][row] = v.x; As[kq + 1][row] = v.y;
            As[kq + 2][row] = v.z; As[kq + 3][row] = v.w;
        }
        {
            int n = tid >> 2, kq = (tid & 3) * 4;
            int nn = n0 + n;
            float4 v = make_float4(0.f, 0.f, 0.f, 0.f);
            if (nn < N && k0 + kq < K)                    // K-guard
                v = *(const float4*)&B[(long)nn * K + k0 + kq];
            Bs[kq + 0][n] = v.x; Bs[kq + 1][n] = v.y;
            Bs[kq + 2][n] = v.z; Bs[kq + 3][n] = v.w;
        }
        __syncthreads();
        #pragma unroll
        for (int k = 0; k < 16; k++) {
            const ull* ap = (const ull*)&As[k][ty * 8];
            ull a0 = ap[0], a1 = ap[1], a2 = ap[2], a3 = ap[3];
            float4 bv = *(const float4*)&Bs[k][tx * 4];
            ull b0 = dup2(bv.x), b1 = dup2(bv.y), b2 = dup2(bv.z), b3 = dup2(bv.w);
            fma2(acc[0][0], a0, b0); fma2(acc[0][1], a0, b1);
            fma2(acc[0][2], a0, b2); fma2(acc[0][3], a0, b3);
            fma2(acc[1][0], a1, b0); fma2(acc[1][1], a1, b1);
            fma2(acc[1][2], a1, b2); fma2(acc[1][3], a1, b3);
            fma2(acc[2][0], a2, b0); fma2(acc[2][1], a2, b1);
            fma2(acc[2][2], a2, b2); fma2(acc[2][3], a2, b3);
            fma2(acc[3][0], a3, b0); fma2(acc[3][1], a3, b1);
            fma2(acc[3][2], a3, b2); fma2(acc[3][3], a3, b3);
        }
        __syncthreads();
    }
    #pragma unroll
    for (int mp = 0; mp < 4; mp++) {
        int m = m0 + ty * 8 + mp * 2;
        #pragma unroll
        for (int j = 0; j < 4; j++) {
            int n = n0 + tx * 4 + j;
            if (n >= N) continue;
            float2 c2 = unpk2(acc[mp][j]);
            float bb = bias ? bias[n] : 0.f;
            float v0 = act_f<ACT>(c2.x + bb), v1 = act_f<ACT>(c2.y + bb);
            if (m     < M) C[(long)(m    ) * ldc + n] = v0;
            if (m + 1 < M) C[(long)(m + 1) * ldc + n] = v1;
        }
    }
}

// ---------------- fused dual fp32 GEMM: e = sigmoid, a = tanh ----------------
__global__ __launch_bounds__(256)
void gemm2_dual(const float* __restrict__ A,
                const float* __restrict__ B1, const float* __restrict__ bias1, float* __restrict__ C1,
                const float* __restrict__ B2, const float* __restrict__ bias2, float* __restrict__ C2,
                int M, int N, int K, int lda_row, int ldc)
{
    __shared__ float As[16][128];
    __shared__ float Bs1[16][64];
    __shared__ float Bs2[16][64];
    const int tid = threadIdx.x;
    const int tx = tid & 15;
    const int ty = tid >> 4;
    const int m0 = blockIdx.y * 128, n0 = blockIdx.x * 64;

    ull acc1[4][4] = {}, acc2[4][4] = {};

    for (int k0 = 0; k0 < K; k0 += 16) {
        #pragma unroll
        for (int u = 0; u < 2; u++) {
            int f4  = tid + u * 256;
            int row = f4 >> 2, kq = (f4 & 3) * 4;
            int m = m0 + row;
            float4 v = make_float4(0.f, 0.f, 0.f, 0.f);
            if (m < M && k0 + kq < K)                     // K-guard (K%4==0)
                v = *(const float4*)&A[(long)m * lda_row + k0 + kq];
            As[kq + 0][row] = v.x; As[kq + 1][row] = v.y;
            As[kq + 2][row] = v.z; As[kq + 3][row] = v.w;
        }
        {
            int n = tid >> 2, kq = (tid & 3) * 4;
            int nn = n0 + n;
            float4 v1 = make_float4(0.f, 0.f, 0.f, 0.f);
            float4 v2 = make_float4(0.f, 0.f, 0.f, 0.f);
            if (nn < N && k0 + kq < K) {                  // K-guard
                v1 = *(const float4*)&B1[(long)nn * K + k0 + kq];
                v2 = *(const float4*)&B2[(long)nn * K + k0 + kq];
            }
            Bs1[kq + 0][n] = v1.x; Bs1[kq + 1][n] = v1.y;
            Bs1[kq + 2][n] = v1.z; Bs1[kq + 3][n] = v1.w;
            Bs2[kq + 0][n] = v2.x; Bs2[kq + 1][n] = v2.y;
            Bs2[kq + 2][n] = v2.z; Bs2[kq + 3][n] = v2.w;
        }
        __syncthreads();
        #pragma unroll
        for (int k = 0; k < 16; k++) {
            const ull* ap = (const ull*)&As[k][ty * 8];
            ull a0 = ap[0], a1 = ap[1], a2 = ap[2], a3 = ap[3];
            float4 bv1 = *(const float4*)&Bs1[k][tx * 4];
            float4 bv2 = *(const float4*)&Bs2[k][tx * 4];
            ull p0 = dup2(bv1.x), p1 = dup2(bv1.y), p2 = dup2(bv1.z), p3 = dup2(bv1.w);
            fma2(acc1[0][0], a0, p0); fma2(acc1[0][1], a0, p1);
            fma2(acc1[0][2], a0, p2); fma2(acc1[0][3], a0, p3);
            fma2(acc1[1][0], a1, p0); fma2(acc1[1][1], a1, p1);
            fma2(acc1[1][2], a1, p2); fma2(acc1[1][3], a1, p3);
            fma2(acc1[2][0], a2, p0); fma2(acc1[2][1], a2, p1);
            fma2(acc1[2][2], a2, p2); fma2(acc1[2][3], a2, p3);
            fma2(acc1[3][0], a3, p0); fma2(acc1[3][1], a3, p1);
            fma2(acc1[3][2], a3, p2); fma2(acc1[3][3], a3, p3);
            ull q0 = dup2(bv2.x), q1 = dup2(bv2.y), q2 = dup2(bv2.z), q3 = dup2(bv2.w);
            fma2(acc2[0][0], a0, q0); fma2(acc2[0][1], a0, q1);
            fma2(acc2[0][2], a0, q2); fma2(acc2[0][3], a0, q3);
            fma2(acc2[1][0], a1, q0); fma2(acc2[1][1], a1, q1);
            fma2(acc2[1][2], a1, q2); fma2(acc2[1][3], a1, q3);
            fma2(acc2[2][0], a2, q0); fma2(acc2[2][1], a2, q1);
            fma2(acc2[2][2], a2, q2); fma2(acc2[2][3], a2, q3);
            fma2(acc2[3][0], a3, q0); fma2(acc2[3][1], a3, q1);
            fma2(acc2[3][2], a3, q2); fma2(acc2[3][3], a3, q3);
        }
        __syncthreads();
    }
    #pragma unroll
    for (int mp = 0; mp < 4; mp++) {
        int m = m0 + ty * 8 + mp * 2;
        #pragma unroll
        for (int j = 0; j < 4; j++) {
            int n = n0 + tx * 4 + j;
            if (n >= N) continue;
            float2 c1 = unpk2(acc1[mp][j]);
            float2 c2 = unpk2(acc2[mp][j]);
            float bb1 = bias1[n], bb2 = bias2[n];
            if (m < M) {
                C1[(long)m * ldc + n] = act_f<1>(c1.x + bb1);
                C2[(long)m * ldc + n] = act_f<2>(c2.x + bb2);
            }
            if (m + 1 < M) {
                C1[(long)(m + 1) * ldc + n] = act_f<1>(c1.y + bb1);
                C2[(long)(m + 1) * ldc + n] = act_f<2>(c2.y + bb2);
            }
        }
    }
}

// ---------------- embedding gather: fp32 + bf16 copies in one pass ----------------
__global__ void gather_kernel(const int* __restrict__ q, const int* __restrict__ r,
                              const float* __restrict__ k_emb, const float* __restrict__ v_emb,
                              float* __restrict__ RK, float* __restrict__ VE,
                              __nv_bfloat16* __restrict__ RKH, __nv_bfloat16* __restrict__ VEH)
{
    int bt = blockIdx.x;
    int j  = threadIdx.x;
    if (j >= 50) return;
    int qv = q[bt];
    int xv = qv + NUMQ * r[bt];
    float4 kv = ((const float4*)(k_emb + (long)qv * Dd))[j];
    float4 vv = ((const float4*)(v_emb + (long)xv * Dd))[j];
    ((float4*)(RK + (long)bt * 400 + 200))[j] = kv;     // fp32 k (wlog)
    ((float4*)(VE + (long)bt * 400))[j]       = vv;     // fp32 v (e/a)
    uint2 kh; kh.x = cvt2(kv.x, kv.y); kh.y = cvt2(kv.z, kv.w);
    uint2 vh; vh.x = cvt2(vv.x, vv.y); vh.y = cvt2(vv.z, vv.w);
    ((uint2*)(RKH + (long)bt * 400 + 200))[j] = kh;     // bf16 k (f GEMM)
    ((uint2*)(VEH + (long)bt * 400))[j]       = vh;     // bf16 v (fl GEMM)
}

// ---------------- row softmax over 50 ----------------
__global__ void softmax50_kernel(const float* __restrict__ lg, float* __restrict__ wout)
{
    int row = blockIdx.x * blockDim.x + threadIdx.x;
    if (row >= BT) return;
    const float* x = lg + (long)row * Mm;
    float e[Mm];
    float mx = -3.4e38f;
    #pragma unroll
    for (int s = 0; s < Mm; s++) { e[s] = x[s]; mx = fmaxf(mx, e[s]); }
    float sum = 0.f;
    #pragma unroll
    for (int s = 0; s < Mm; s++) { e[s] = expf(e[s] - mx); sum += e[s]; }
    float inv = 1.f / sum;
    float* o = wout + (long)row * Mm;
    #pragma unroll
    for (int s = 0; s < Mm; s++) o[s] = e[s] * inv;
}

// ---------------- memory scan (round-4 structure; read emitted directly as bf16) ----------------
__global__ void scan_kernel(const float* __restrict__ w, const float* __restrict__ e,
                            const float* __restrict__ a, const float* __restrict__ Mv0,
                            float* __restrict__ MvOut, __nv_bfloat16* __restrict__ RKH)
{
    int b = blockIdx.x;
    int d = blockIdx.y * 50 + threadIdx.x;
    bool active = (threadIdx.x < 50);
    __shared__ float ws[Mm];
    float mv[Mm];
    if (active) {
        #pragma unroll
        for (int s = 0; s < Mm; s++) mv[s] = Mv0[s * Dd + d];
    }
    const float* wb = w + (long)b * Nn * Mm;
    const float* eb = e + (long)b * Nn * Dd;
    const float* ab = a + (long)b * Nn * Dd;
    float* mb = MvOut + (long)b * MV_PER_B;
    __nv_bfloat16* rb = RKH + (long)b * Nn * 400;

    for (int t = 0; t < Nn; t++) {
        if (threadIdx.x < Mm) ws[threadIdx.x] = wb[t * Mm + threadIdx.x];
        __syncthreads();
        if (active) {
            float ed = eb[t * Dd + d];
            float ad = ab[t * Dd + d];
            float* mp = mb + (long)t * (Mm * Dd) + d;
            float rd = 0.f;
            #pragma unroll
            for (int s = 0; s < Mm; s++) {
                float m_ = mv[s];
                mp[s * Dd] = m_;
                float wv = ws[s];
                rd += wv * m_;
                mv[s] = m_ + wv * (ad - ed * m_);
            }
            rb[t * 400 + d] = __float2bfloat16(rd);     // bf16 read (f GEMM)
        }
        __syncthreads();
    }
    if (active) {
        float* mp = mb + (long)Nn * (Mm * Dd) + d;
        #pragma unroll
        for (int s = 0; s < Mm; s++) mp[s * Dd] = mv[s];
    }
}

// ---------------- final projection ----------------
__global__ void p_kernel(const float* __restrict__ f, const float* __restrict__ fl,
                         const float* __restrict__ Wp, const float* __restrict__ bp,
                         float* __restrict__ outp)
{
    int b = blockIdx.x;
    __shared__ float wsh[400];
    for (int i = threadIdx.x; i < 400; i += blockDim.x) wsh[i] = Wp[i];
    __syncthreads();
    int t = blockIdx.y * 128 + threadIdx.x;
    if (t < Nn) {
        float acc = bp[0];
        const float* flb = fl + (long)b * Nn * Dd;
        #pragma unroll 4
        for (int i = 0; i < Nn; i++)
            acc += flb[(long)i * Dd + t] * wsh[200 + i];
        const float4* fb = (const float4*)(f + ((long)b * Nn + t) * Dd);
        #pragma unroll 5
        for (int dq = 0; dq < 50; dq++) {
            float4 v = fb[dq];
            acc += v.x * wsh[dq*4] + v.y * wsh[dq*4+1] + v.z * wsh[dq*4+2] + v.w * wsh[dq*4+3];
        }
        outp[b * Nn + t] = 1.f / (1.f + expf(-acc));
    }
}

// ---------------- host ----------------
extern "C" void kernel_launch(void* const* d_in, const int* in_sizes, int n_in,
                              void* d_out, int out_size)
{
    const int*   q      = (const int*)  d_in[0];
    const int*   r      = (const int*)  d_in[1];
    const float* bert   = (const float*)d_in[2];
    const float* k_emb  = (const float*)d_in[3];
    const float* v_emb  = (const float*)d_in[4];
    const float* Mk     = (const float*)d_in[5];
    const float* Mv0    = (const float*)d_in[6];
    const float* W_at   = (const float*)d_in[7];
    const float* b_at   = (const float*)d_in[8];
    const float* W_at2  = (const float*)d_in[9];
    const float* b_at2  = (const float*)d_in[10];
    const float* W_fus  = (const float*)d_in[11];
    const float* b_fus  = (const float*)d_in[12];
    const float* W_e    = (const float*)d_in[13];
    const float* b_e    = (const float*)d_in[14];
    const float* W_a    = (const float*)d_in[15];
    const float* b_a    = (const float*)d_in[16];
    const float* W_f    = (const float*)d_in[17];
    const float* b_f    = (const float*)d_in[18];
    const float* W_p    = (const float*)d_in[19];
    const float* b_p    = (const float*)d_in[20];

    float* outp  = (float*)d_out;
    float* outMv = outp + OUT_P_SIZE;
    float* outw  = outMv + OUT_MV_SIZE;

    __nv_bfloat16 *bertH, *emT, *WatH, *Wat2H, *WfH, *WfusH, *RKH, *VEH;
    float *VE, *RK, *e_s, *a_s, *f_s, *fl_s, *wlog;
    cudaGetSymbolAddress((void**)&bertH, g_bertH);
    cudaGetSymbolAddress((void**)&emT,   g_emT);
    cudaGetSymbolAddress((void**)&WatH,  g_WatH);
    cudaGetSymbolAddress((void**)&Wat2H, g_Wat2H);
    cudaGetSymbolAddress((void**)&WfH,   g_WfH);
    cudaGetSymbolAddress((void**)&WfusH, g_WfusH);
    cudaGetSymbolAddress((void**)&RKH,   g_RKH);
    cudaGetSymbolAddress((void**)&VEH,   g_VEH);
    cudaGetSymbolAddress((void**)&VE,    g_VE);
    cudaGetSymbolAddress((void**)&RK,    g_RK);
    cudaGetSymbolAddress((void**)&e_s,   g_e);
    cudaGetSymbolAddress((void**)&a_s,   g_a);
    cudaGetSymbolAddress((void**)&f_s,   g_f);
    cudaGetSymbolAddress((void**)&fl_s,  g_fl);
    cudaGetSymbolAddress((void**)&wlog,  g_wlog);

    // 1. gather k,v (fp32 + bf16)
    gather_kernel<<<BT, 64>>>(q, r, k_emb, v_emb, RK, VE, RKH, VEH);

    // 2. bertH = bf16(bert)
    cvt_kernel<<<24576, 256>>>(bert, bertH, 6291456L);

    // 3. weights -> bf16
    wcvt_kernel<<<407, 256>>>(W_at, W_at2, W_f, W_fus, WatH, Wat2H, WfH, WfusH);

    // 4. em = bertH @ WatH^T + b_at -> bf16 transposed em_T[b][d][l]  [capture slot]
    mma_gemmH<0,1><<<dim3(4, 256, 1), 256>>>(
        bertH, WatH, b_at, emT, Bsz*Lb, Dd, Hb, 0, 0, Hb, 0);

    // 5. em_at[b] = em_T[b] @ Wat2H^T + b_at2 -> VEH[...,200:400] bf16 (direct)
    mma_gemmH<0,2><<<dim3(4, 2, Bsz), 256>>>(
        emT, Wat2H, b_at2, VEH + 200, Dd, Dd, Lb,
        (long)Dd * Lb, (long)Nn * 400, Lb, 400);

    // 6. w logits = k @ Mk^T  (fp32, precision-critical)
    gemm2<0><<<dim3(1, 100, 1), 256>>>(
        RK + 200, Mk, (const float*)nullptr, wlog, BT, Mm, Dd, 400, Mm);

    // 7. softmax -> w output
    softmax50_kernel<<<100, 128>>>(wlog, outw);

    // 8. fused e/a (fp32)
    gemm2_dual<<<dim3(4, 100, 1), 256>>>(
        VE, W_e, b_e, e_s, W_a, b_a, a_s, BT, Dd, Dd, 400, Dd);

    // 9. memory scan: Mv + bf16 read -> RKH[...,0:200]
    scan_kernel<<<dim3(Bsz, 4, 1), 64>>>(outw, e_s, a_s, Mv0, outMv, RKH);

    // 10. f = tanh(RKH @ WfH^T + b_f)
    mma_gemmH<2,0><<<dim3(4, 100, 1), 256>>>(
        RKH, WfH, b_f, f_s, BT, Dd, 400, 0, 0, 400, Dd);

    // 11. f_l = relu(VEH @ WfusH^T + b_fus)
    mma_gemmH<3,0><<<dim3(4, 100, 1), 256>>>(
        VEH, WfusH, b_fus, fl_s, BT, Dd, 400, 0, 0, 400, Dd);

    // 12. p
    p_kernel<<<dim3(Bsz, 2, 1), 128>>>(f_s, fl_s, W_p, b_p, outp);
}